// round 4
// baseline (speedup 1.0000x reference)
#include <cuda_runtime.h>
#include <cstdint>

// Problem dims
#define B_ 8
#define L_ 1024
#define D_ 512
#define H_ 8
#define DK_ 64
#define BL_ (B_ * L_)               // 8192
#define ATT_OFF ((size_t)BL_ * D_)  // start of attn in d_out

// Projection GEMM tile config
#define BM 128
#define BN 64
#define BK 32
#define NTHR 256

// Fused scores+softmax config
#define QB2 16
#define CH 128
#define NCH (L_ / CH)   // 8

// Scratch (static device globals — no allocation)
__device__ float g_Q[BL_ * D_];
__device__ float g_K[BL_ * D_];
__device__ float g_V[BL_ * D_];
__device__ float g_O[BL_ * D_];    // attn@V result; later reused for s2 output
__device__ float g_O2[BL_ * D_];   // fc output
__device__ float g_X[BL_ * D_];    // silu(film(h))
__device__ float g_lat[B_ * 2 * D_];

// ---------------------------------------------------------------------------
// tf32 helpers
// ---------------------------------------------------------------------------
__device__ __forceinline__ float tf32r(float x) {
    uint32_t o;
    asm("cvt.rna.tf32.f32 %0, %1;" : "=r"(o) : "f"(x));
    return __uint_as_float(o);
}

__device__ __forceinline__ void mma_tf32(float c[4], const float a[4], const float b[2]) {
    asm volatile(
        "mma.sync.aligned.m16n8k8.row.col.f32.tf32.tf32.f32 "
        "{%0,%1,%2,%3}, {%4,%5,%6,%7}, {%8,%9}, {%0,%1,%2,%3};"
        : "+f"(c[0]), "+f"(c[1]), "+f"(c[2]), "+f"(c[3])
        : "r"(__float_as_uint(a[0])), "r"(__float_as_uint(a[1])),
          "r"(__float_as_uint(a[2])), "r"(__float_as_uint(a[3])),
          "r"(__float_as_uint(b[0])), "r"(__float_as_uint(b[1])));
}

// ---------------------------------------------------------------------------
// Fused scores + softmax. One CTA per (b,h, 16-query block); S tile held in
// registers (acc[8][2][4] per thread); exact fp32 softmax; single attn write.
// grid (L/QB2=64, B*H=64), 256 threads.
// ---------------------------------------------------------------------------
__global__ void __launch_bounds__(256) k_scsm(float* __restrict__ attn) {
    __shared__ float Qs[QB2][68];
    __shared__ float Ks[CH][68];     // reused as write-staging [16][132]
    __shared__ float red[8][16];
    __shared__ float rstat[16];

    const int t = threadIdx.x;
    const int lane = t & 31, w = t >> 5;
    const int g = lane >> 2, tg = lane & 3;
    const int z = blockIdx.y;
    const int b = z >> 3, h = z & 7;
    const int q0 = blockIdx.x * QB2;

    const float* Qg = g_Q + (size_t)b * L_ * D_ + h * DK_;
    const float* Kg = g_K + (size_t)b * L_ * D_ + h * DK_;
    float* attn_b = attn + (size_t)z * L_ * L_;

    // ---- load Q tile (16 x 64): 256 float4, one per thread ----
    {
        int r = t >> 4, c4 = (t & 15) << 2;
        float4 v = *(const float4*)(Qg + (size_t)(q0 + r) * D_ + c4);
        Qs[r][c4 + 0] = tf32r(v.x);
        Qs[r][c4 + 1] = tf32r(v.y);
        Qs[r][c4 + 2] = tf32r(v.z);
        Qs[r][c4 + 3] = tf32r(v.w);
    }

    float acc[NCH][2][4] = {};

    #pragma unroll
    for (int kc = 0; kc < NCH; kc++) {
        __syncthreads();
        #pragma unroll
        for (int i = 0; i < 8; i++) {
            int idx = t + i * 256;
            int r = idx >> 4, c4 = (idx & 15) << 2;
            float4 v = *(const float4*)(Kg + (size_t)(kc * CH + r) * D_ + c4);
            Ks[r][c4 + 0] = tf32r(v.x);
            Ks[r][c4 + 1] = tf32r(v.y);
            Ks[r][c4 + 2] = tf32r(v.z);
            Ks[r][c4 + 3] = tf32r(v.w);
        }
        __syncthreads();

        #pragma unroll
        for (int ks = 0; ks < DK_; ks += 8) {
            float a[4];
            a[0] = Qs[g][ks + tg];
            a[1] = Qs[g + 8][ks + tg];
            a[2] = Qs[g][ks + tg + 4];
            a[3] = Qs[g + 8][ks + tg + 4];
            #pragma unroll
            for (int nt = 0; nt < 2; nt++) {
                int n = w * 16 + nt * 8 + g;
                float bf[2];
                bf[0] = Ks[n][ks + tg];
                bf[1] = Ks[n][ks + tg + 4];
                mma_tf32(acc[kc][nt], a, bf);
            }
        }
    }

    // ---- softmax over register-resident rows (rows g and g+8) ----
    float m0 = -1e30f, m1 = -1e30f;
    #pragma unroll
    for (int kc = 0; kc < NCH; kc++)
        #pragma unroll
        for (int nt = 0; nt < 2; nt++) {
            m0 = fmaxf(m0, fmaxf(acc[kc][nt][0], acc[kc][nt][1]));
            m1 = fmaxf(m1, fmaxf(acc[kc][nt][2], acc[kc][nt][3]));
        }
    m0 *= 0.125f; m1 *= 0.125f;
    // quad reduce (lanes sharing g)
    m0 = fmaxf(m0, __shfl_xor_sync(~0u, m0, 1));
    m0 = fmaxf(m0, __shfl_xor_sync(~0u, m0, 2));
    m1 = fmaxf(m1, __shfl_xor_sync(~0u, m1, 1));
    m1 = fmaxf(m1, __shfl_xor_sync(~0u, m1, 2));
    if (tg == 0) { red[w][g] = m0; red[w][g + 8] = m1; }
    __syncthreads();
    if (t < 16) {
        float m = red[0][t];
        #pragma unroll
        for (int j = 1; j < 8; j++) m = fmaxf(m, red[j][t]);
        rstat[t] = m;
    }
    __syncthreads();
    m0 = rstat[g]; m1 = rstat[g + 8];
    __syncthreads();

    float s0 = 0.f, s1 = 0.f;
    #pragma unroll
    for (int kc = 0; kc < NCH; kc++)
        #pragma unroll
        for (int nt = 0; nt < 2; nt++) {
            float e0 = __expf(acc[kc][nt][0] * 0.125f - m0);
            float e1 = __expf(acc[kc][nt][1] * 0.125f - m0);
            float e2 = __expf(acc[kc][nt][2] * 0.125f - m1);
            float e3 = __expf(acc[kc][nt][3] * 0.125f - m1);
            acc[kc][nt][0] = e0; acc[kc][nt][1] = e1;
            acc[kc][nt][2] = e2; acc[kc][nt][3] = e3;
            s0 += e0 + e1; s1 += e2 + e3;
        }
    s0 += __shfl_xor_sync(~0u, s0, 1);
    s0 += __shfl_xor_sync(~0u, s0, 2);
    s1 += __shfl_xor_sync(~0u, s1, 1);
    s1 += __shfl_xor_sync(~0u, s1, 2);
    if (tg == 0) { red[w][g] = s0; red[w][g + 8] = s1; }
    __syncthreads();
    if (t < 16) {
        float s = red[0][t];
        #pragma unroll
        for (int j = 1; j < 8; j++) s += red[j][t];
        rstat[t] = 1.0f / s;
    }
    __syncthreads();
    const float inv0 = rstat[g], inv1 = rstat[g + 8];

    // ---- staged coalesced writes, chunk by chunk ----
    float* Ws = &Ks[0][0];   // [16][132]
    #pragma unroll
    for (int kc = 0; kc < NCH; kc++) {
        __syncthreads();
        #pragma unroll
        for (int nt = 0; nt < 2; nt++) {
            int c = w * 16 + nt * 8 + tg * 2;
            Ws[g * 132 + c]           = acc[kc][nt][0] * inv0;
            Ws[g * 132 + c + 1]       = acc[kc][nt][1] * inv0;
            Ws[(g + 8) * 132 + c]     = acc[kc][nt][2] * inv1;
            Ws[(g + 8) * 132 + c + 1] = acc[kc][nt][3] * inv1;
        }
        __syncthreads();
        #pragma unroll
        for (int i = 0; i < 2; i++) {
            int idx = t + i * 256;
            int r = idx >> 5, c4 = (idx & 31) << 2;
            *(float4*)(attn_b + (size_t)(q0 + r) * L_ + kc * CH + c4) =
                *(const float4*)&Ws[r * 132 + c4];
        }
    }
}

// ---------------------------------------------------------------------------
// TF32 tensor-core GEMM tile body (projections / attnv / fc / s2).
// BT=1: Bg is [N][K] row-major; BT=0: Bg is [K][N] row-major.
// ---------------------------------------------------------------------------
__device__ __forceinline__ void gemm_tc_nn(
    const float* __restrict__ A, const float* __restrict__ Bg,
    const float* __restrict__ bias, float* __restrict__ C,
    int K, int lda, int ldb, int ldc)
{
    __shared__ float As[BM][BK + 4];
    __shared__ float Bs[BN][BK + 4];

    const int t = threadIdx.x;
    const int lane = t & 31, warp = t >> 5;
    const int wm = warp & 3, wn = warp >> 2;
    const int g = lane >> 2, tg = lane & 3;
    const int row0 = blockIdx.y * BM;
    const int col0 = blockIdx.x * BN;

    float acc[2][4][4] = {};

    for (int k0 = 0; k0 < K; k0 += BK) {
        #pragma unroll
        for (int i = 0; i < 4; i++) {
            int idx = t + i * NTHR;
            int r = idx >> 3, c4 = (idx & 7) << 2;
            float4 v = *(const float4*)(A + (size_t)(row0 + r) * lda + k0 + c4);
            As[r][c4 + 0] = tf32r(v.x);
            As[r][c4 + 1] = tf32r(v.y);
            As[r][c4 + 2] = tf32r(v.z);
            As[r][c4 + 3] = tf32r(v.w);
        }
        #pragma unroll
        for (int i = 0; i < 2; i++) {
            int idx = t + i * NTHR;
            int kk = idx >> 4, n4 = (idx & 15) << 2;
            float4 v = *(const float4*)(Bg + (size_t)(k0 + kk) * ldb + col0 + n4);
            Bs[n4 + 0][kk] = tf32r(v.x);
            Bs[n4 + 1][kk] = tf32r(v.y);
            Bs[n4 + 2][kk] = tf32r(v.z);
            Bs[n4 + 3][kk] = tf32r(v.w);
        }
        __syncthreads();

        #pragma unroll
        for (int ks = 0; ks < BK; ks += 8) {
            float a[2][4], bfr[4][2];
            #pragma unroll
            for (int mt = 0; mt < 2; mt++) {
                int r = wm * 32 + mt * 16 + g;
                a[mt][0] = As[r][ks + tg];
                a[mt][1] = As[r + 8][ks + tg];
                a[mt][2] = As[r][ks + tg + 4];
                a[mt][3] = As[r + 8][ks + tg + 4];
            }
            #pragma unroll
            for (int nt = 0; nt < 4; nt++) {
                int n = wn * 32 + nt * 8 + g;
                bfr[nt][0] = Bs[n][ks + tg];
                bfr[nt][1] = Bs[n][ks + tg + 4];
            }
            #pragma unroll
            for (int mt = 0; mt < 2; mt++)
                #pragma unroll
                for (int nt = 0; nt < 4; nt++)
                    mma_tf32(acc[mt][nt], a[mt], bfr[nt]);
        }
        __syncthreads();
    }

    #pragma unroll
    for (int mt = 0; mt < 2; mt++) {
        #pragma unroll
        for (int nt = 0; nt < 4; nt++) {
            int r = row0 + wm * 32 + mt * 16 + g;
            int c = col0 + wn * 32 + nt * 8 + tg * 2;
            float b0 = 0.f, b1 = 0.f;
            if (bias) { b0 = bias[c]; b1 = bias[c + 1]; }
            *(float2*)(C + (size_t)r * ldc + c) =
                make_float2(acc[mt][nt][0] + b0, acc[mt][nt][1] + b1);
            *(float2*)(C + (size_t)(r + 8) * ldc + c) =
                make_float2(acc[mt][nt][2] + b0, acc[mt][nt][3] + b1);
        }
    }
}

__global__ void __launch_bounds__(NTHR) k_proj_q(const float* __restrict__ A,
        const float* __restrict__ W, const float* __restrict__ bias) {
    gemm_tc_nn(A, W, bias, g_Q, D_, D_, D_, D_);
}
__global__ void __launch_bounds__(NTHR) k_proj_k(const float* __restrict__ A,
        const float* __restrict__ W, const float* __restrict__ bias) {
    gemm_tc_nn(A, W, bias, g_K, D_, D_, D_, D_);
}
__global__ void __launch_bounds__(NTHR) k_proj_v(const float* __restrict__ A,
        const float* __restrict__ W, const float* __restrict__ bias) {
    gemm_tc_nn(A, W, bias, g_V, D_, D_, D_, D_);
}

// o = attn @ V. grid (1, L/BM=8, 64)
__global__ void __launch_bounds__(NTHR) k_attnv(const float* __restrict__ attn) {
    int z = blockIdx.z;
    int b = z >> 3, h = z & 7;
    const float* Ab = attn + (size_t)z * L_ * L_;
    const float* Bb = g_V + (size_t)b * L_ * D_ + h * DK_;
    float* Cb = g_O + (size_t)b * L_ * D_ + h * DK_;
    // Bg is [K][N] with ldb = D_ (V rows are keys)
    gemm_tc_nn(Ab, Bb, nullptr, Cb, L_, L_, D_, D_);
}

__global__ void __launch_bounds__(NTHR) k_fc(const float* __restrict__ W,
        const float* __restrict__ bias) {
    gemm_tc_nn(g_O, W, bias, g_O2, D_, D_, D_, D_);
}
__global__ void __launch_bounds__(NTHR) k_s2(const float* __restrict__ W,
        const float* __restrict__ bias) {
    gemm_tc_nn(g_X, W, bias, g_O, D_, D_, D_, D_);
}

// ---------------------------------------------------------------------------
// lat = silu(latent) @ Ws1 + bs1 -> g_lat [B, 2D]. grid (8,8), 128 thr
// ---------------------------------------------------------------------------
__global__ void k_lat(const float* __restrict__ latent, const float* __restrict__ Ws1,
                      const float* __restrict__ bs1) {
    int b = blockIdx.x;
    __shared__ float sl[D_];
    for (int i = threadIdx.x; i < D_; i += 128) {
        float x = latent[b * D_ + i];
        sl[i] = x / (1.0f + __expf(-x));
    }
    __syncthreads();
    int j = blockIdx.y * 128 + threadIdx.x;
    float acc = bs1[j];
    for (int k = 0; k < D_; k++) acc += sl[k] * Ws1[(size_t)k * (2 * D_) + j];
    g_lat[b * (2 * D_) + j] = acc;
}

// film: X = silu( LN(o2; en) * (1+scale) + shift ). one block (128 thr) per row
__global__ void k_film(const float* __restrict__ en_g, const float* __restrict__ en_b) {
    int row = blockIdx.x;
    int b = row >> 10;
    int t = threadIdx.x;
    float4 v = ((const float4*)(g_O2 + (size_t)row * D_))[t];
    __shared__ float red[128];

    red[t] = v.x + v.y + v.z + v.w;
    __syncthreads();
    for (int s = 64; s > 0; s >>= 1) {
        if (t < s) red[t] += red[t + s];
        __syncthreads();
    }
    float mean = red[0] * (1.0f / D_);
    __syncthreads();

    float dx = v.x - mean, dy = v.y - mean, dz = v.z - mean, dw = v.w - mean;
    red[t] = dx * dx + dy * dy + dz * dz + dw * dw;
    __syncthreads();
    for (int s = 64; s > 0; s >>= 1) {
        if (t < s) red[t] += red[t + s];
        __syncthreads();
    }
    float rstd = rsqrtf(red[0] * (1.0f / D_) + 1e-5f);

    int j = t * 4;
    float4 g4 = ((const float4*)en_g)[t];
    float4 b4 = ((const float4*)en_b)[t];
    float4 sc = *(const float4*)(g_lat + b * (2 * D_) + j);
    float4 sh = *(const float4*)(g_lat + b * (2 * D_) + D_ + j);

    float4 o;
    {
        float h;
        h = (dx * rstd * g4.x + b4.x) * (1.0f + sc.x) + sh.x; o.x = h / (1.0f + __expf(-h));
        h = (dy * rstd * g4.y + b4.y) * (1.0f + sc.y) + sh.y; o.y = h / (1.0f + __expf(-h));
        h = (dz * rstd * g4.z + b4.z) * (1.0f + sc.z) + sh.z; o.z = h / (1.0f + __expf(-h));
        h = (dw * rstd * g4.w + b4.w) * (1.0f + sc.w) + sh.w; o.w = h / (1.0f + __expf(-h));
    }
    ((float4*)(g_X + (size_t)row * D_))[t] = o;
}

// out = LN(h2 + residual; ln, eps=1e-6). one block (128 thr) per row
__global__ void k_final(const float* __restrict__ resid, const float* __restrict__ ln_g,
                        const float* __restrict__ ln_b, float* __restrict__ out) {
    int row = blockIdx.x;
    int t = threadIdx.x;
    float4 v = ((const float4*)(g_O + (size_t)row * D_))[t];
    float4 r = ((const float4*)(resid + (size_t)row * D_))[t];
    v.x += r.x; v.y += r.y; v.z += r.z; v.w += r.w;
    __shared__ float red[128];

    red[t] = v.x + v.y + v.z + v.w;
    __syncthreads();
    for (int s = 64; s > 0; s >>= 1) {
        if (t < s) red[t] += red[t + s];
        __syncthreads();
    }
    float mean = red[0] * (1.0f / D_);
    __syncthreads();

    float dx = v.x - mean, dy = v.y - mean, dz = v.z - mean, dw = v.w - mean;
    red[t] = dx * dx + dy * dy + dz * dz + dw * dw;
    __syncthreads();
    for (int s = 64; s > 0; s >>= 1) {
        if (t < s) red[t] += red[t + s];
        __syncthreads();
    }
    float rstd = rsqrtf(red[0] * (1.0f / D_) + 1e-6f);

    float4 g4 = ((const float4*)ln_g)[t];
    float4 b4 = ((const float4*)ln_b)[t];
    float4 o;
    o.x = dx * rstd * g4.x + b4.x;
    o.y = dy * rstd * g4.y + b4.y;
    o.z = dz * rstd * g4.z + b4.z;
    o.w = dw * rstd * g4.w + b4.w;
    ((float4*)(out + (size_t)row * D_))[t] = o;
}

// ---------------------------------------------------------------------------
extern "C" void kernel_launch(void* const* d_in, const int* in_sizes, int n_in,
                              void* d_out, int out_size) {
    const float* q      = (const float*)d_in[0];
    const float* k      = (const float*)d_in[1];
    const float* v      = (const float*)d_in[2];
    const float* latent = (const float*)d_in[3];
    const float* Wq  = (const float*)d_in[4];
    const float* bq  = (const float*)d_in[5];
    const float* Wk  = (const float*)d_in[6];
    const float* bk  = (const float*)d_in[7];
    const float* Wv  = (const float*)d_in[8];
    const float* bv  = (const float*)d_in[9];
    const float* Wfc = (const float*)d_in[10];
    const float* bfc = (const float*)d_in[11];
    const float* Ws1 = (const float*)d_in[12];
    const float* bs1 = (const float*)d_in[13];
    const float* Ws2 = (const float*)d_in[14];
    const float* bs2 = (const float*)d_in[15];
    const float* en_g = (const float*)d_in[16];
    const float* en_b = (const float*)d_in[17];
    const float* ln_g = (const float*)d_in[18];
    const float* ln_b = (const float*)d_in[19];

    float* out  = (float*)d_out;
    float* attn = out + ATT_OFF;

    dim3 t256(NTHR);
    dim3 gProj(D_ / BN, BL_ / BM);          // (8, 64)

    k_proj_q<<<gProj, t256>>>(q, Wq, bq);
    k_proj_k<<<gProj, t256>>>(k, Wk, bk);
    k_proj_v<<<gProj, t256>>>(v, Wv, bv);

    k_scsm<<<dim3(L_ / QB2, B_ * H_), 256>>>(attn);
    k_attnv<<<dim3(1, L_ / BM, B_ * H_), t256>>>(attn);

    k_fc<<<gProj, t256>>>(Wfc, bfc);
    k_lat<<<dim3(B_, 8), 128>>>(latent, Ws1, bs1);
    k_film<<<BL_, 128>>>(en_g, en_b);
    k_s2<<<gProj, t256>>>(Ws2, bs2);
    k_final<<<BL_, 128>>>(q, ln_g, ln_b, out);
}

// round 5
// speedup vs baseline: 1.9338x; 1.9338x over previous
#include <cuda_runtime.h>
#include <cstdint>

// Problem dims
#define B_ 8
#define L_ 1024
#define D_ 512
#define H_ 8
#define DK_ 64
#define BL_ (B_ * L_)               // 8192
#define ATT_OFF ((size_t)BL_ * D_)  // start of attn in d_out

// GEMM tile config
#define BM 128
#define BN 64
#define BK 32
#define NTHR 256

#define ASZ (BM * 36)       // A stage floats
#define BSZ (BK * 72)       // B stage floats
#define SMEM_GEMM ((2 * ASZ + 2 * BSZ + 128) * 4)        // 55808 B
#define SMEM_SC   ((128 * 68 + 64 * 68 + 256) * 4)       // 53248 B

// Scratch (static device globals — no allocation)
__device__ float g_Q[BL_ * D_];
__device__ float g_K[BL_ * D_];
__device__ float g_V[BL_ * D_];
__device__ float g_O[BL_ * D_];
__device__ float g_O2[BL_ * D_];
__device__ float g_X[BL_ * D_];
__device__ float g_lat[B_ * 2 * D_];
__device__ float g_psum[(size_t)B_ * H_ * 16 * L_];   // partial row sums
__device__ float g_rinv[(size_t)B_ * H_ * L_];        // 1/rowsum

// ---------------------------------------------------------------------------
// helpers
// ---------------------------------------------------------------------------
__device__ __forceinline__ float tf32r(float x) {
    uint32_t o;
    asm("cvt.rna.tf32.f32 %0, %1;" : "=r"(o) : "f"(x));
    return __uint_as_float(o);
}

__device__ __forceinline__ void mma_tf32(float c[4], const float a[4], const float b[2]) {
    asm volatile(
        "mma.sync.aligned.m16n8k8.row.col.f32.tf32.tf32.f32 "
        "{%0,%1,%2,%3}, {%4,%5,%6,%7}, {%8,%9}, {%0,%1,%2,%3};"
        : "+f"(c[0]), "+f"(c[1]), "+f"(c[2]), "+f"(c[3])
        : "r"(__float_as_uint(a[0])), "r"(__float_as_uint(a[1])),
          "r"(__float_as_uint(a[2])), "r"(__float_as_uint(a[3])),
          "r"(__float_as_uint(b[0])), "r"(__float_as_uint(b[1])));
}

__device__ __forceinline__ void cp16(float* dst_smem, const float* src) {
    uint32_t d = (uint32_t)__cvta_generic_to_shared(dst_smem);
    asm volatile("cp.async.cg.shared.global [%0], [%1], 16;" :: "r"(d), "l"(src));
}
#define CP_COMMIT() asm volatile("cp.async.commit_group;")
#define CP_WAIT0()  asm volatile("cp.async.wait_group 0;")
#define CP_WAIT1()  asm volatile("cp.async.wait_group 1;")

// ---------------------------------------------------------------------------
// Double-buffered cp.async TF32 GEMM. C[BM x BN] tile at (by*BM, bx*BN).
// A row-major [M][K] (lda), Bg row-major [K][N] (ldb).
// SC: scale output rows by rinvg[row]; write back A*rinv (normalized attn)
//     to wback with A's indexing.
// ---------------------------------------------------------------------------
template <bool SC>
__device__ __forceinline__ void gemm_pipe(
    const float* __restrict__ A, const float* __restrict__ Bg,
    const float* __restrict__ bias, float* __restrict__ C,
    int K, int lda, int ldb, int ldc,
    const float* __restrict__ rinvg, float* __restrict__ wback)
{
    extern __shared__ float sm[];
    float* Asm = sm;                    // [2][BM][36]
    float* Bsm = sm + 2 * ASZ;          // [2][BK][72]
    float* sRinv = Bsm + 2 * BSZ;       // [128]

    const int t = threadIdx.x;
    const int lane = t & 31, w = t >> 5;
    const int wm = w & 3, wn = w >> 2;
    const int g = lane >> 2, tg = lane & 3;
    const int row0 = blockIdx.y * BM;
    const int col0 = blockIdx.x * BN;

    if (SC && t < BM) sRinv[t] = rinvg[row0 + t];

    float acc[2][4][4] = {};

    // prologue: stage 0
    {
        float* Ad = Asm;
        float* Bd = Bsm;
        #pragma unroll
        for (int i = 0; i < 4; i++) {
            int idx = t + i * NTHR, r = idx >> 3, c4 = (idx & 7) << 2;
            cp16(Ad + r * 36 + c4, A + (size_t)(row0 + r) * lda + c4);
        }
        #pragma unroll
        for (int i = 0; i < 2; i++) {
            int idx = t + i * NTHR, r = idx >> 4, c4 = (idx & 15) << 2;
            cp16(Bd + r * 72 + c4, Bg + (size_t)r * ldb + col0 + c4);
        }
        CP_COMMIT();
    }

    int buf = 0;
    for (int k0 = 0; k0 < K; k0 += BK) {
        if (k0 + BK < K) {
            float* Ad = Asm + (buf ^ 1) * ASZ;
            float* Bd = Bsm + (buf ^ 1) * BSZ;
            int kn = k0 + BK;
            #pragma unroll
            for (int i = 0; i < 4; i++) {
                int idx = t + i * NTHR, r = idx >> 3, c4 = (idx & 7) << 2;
                cp16(Ad + r * 36 + c4, A + (size_t)(row0 + r) * lda + kn + c4);
            }
            #pragma unroll
            for (int i = 0; i < 2; i++) {
                int idx = t + i * NTHR, r = idx >> 4, c4 = (idx & 15) << 2;
                cp16(Bd + r * 72 + c4, Bg + (size_t)(kn + r) * ldb + col0 + c4);
            }
            CP_COMMIT();
            CP_WAIT1();
        } else {
            CP_WAIT0();
        }
        __syncthreads();

        float* Ab = Asm + buf * ASZ;
        float* Bb = Bsm + buf * BSZ;

        if (SC) {
            // write normalized attn chunk back to gmem
            #pragma unroll
            for (int i = 0; i < 4; i++) {
                int idx = t + i * NTHR, r = idx >> 3, c4 = (idx & 7) << 2;
                float4 v = *(const float4*)(Ab + r * 36 + c4);
                float s = sRinv[r];
                v.x *= s; v.y *= s; v.z *= s; v.w *= s;
                *(float4*)(wback + (size_t)(row0 + r) * lda + k0 + c4) = v;
            }
        }

        #pragma unroll
        for (int ks = 0; ks < BK; ks += 8) {
            float a[2][4], bf[4][2];
            #pragma unroll
            for (int mt = 0; mt < 2; mt++) {
                int r = wm * 32 + mt * 16 + g;
                a[mt][0] = tf32r(Ab[r * 36 + ks + tg]);
                a[mt][1] = tf32r(Ab[(r + 8) * 36 + ks + tg]);
                a[mt][2] = tf32r(Ab[r * 36 + ks + tg + 4]);
                a[mt][3] = tf32r(Ab[(r + 8) * 36 + ks + tg + 4]);
            }
            #pragma unroll
            for (int nt = 0; nt < 4; nt++) {
                int n = wn * 32 + nt * 8 + g;
                bf[nt][0] = tf32r(Bb[(ks + tg) * 72 + n]);
                bf[nt][1] = tf32r(Bb[(ks + tg + 4) * 72 + n]);
            }
            #pragma unroll
            for (int mt = 0; mt < 2; mt++)
                #pragma unroll
                for (int nt = 0; nt < 4; nt++)
                    mma_tf32(acc[mt][nt], a[mt], bf[nt]);
        }
        __syncthreads();
        buf ^= 1;
    }

    // epilogue
    #pragma unroll
    for (int mt = 0; mt < 2; mt++) {
        #pragma unroll
        for (int nt = 0; nt < 4; nt++) {
            int rl = wm * 32 + mt * 16 + g;
            int r = row0 + rl;
            int c = col0 + wn * 32 + nt * 8 + tg * 2;
            float s0 = 1.f, s1 = 1.f;
            if (SC) { s0 = sRinv[rl]; s1 = sRinv[rl + 8]; }
            float b0 = 0.f, b1 = 0.f;
            if (bias) { b0 = bias[c]; b1 = bias[c + 1]; }
            *(float2*)(C + (size_t)r * ldc + c) =
                make_float2(acc[mt][nt][0] * s0 + b0, acc[mt][nt][1] * s0 + b1);
            *(float2*)(C + (size_t)(r + 8) * ldc + c) =
                make_float2(acc[mt][nt][2] * s1 + b0, acc[mt][nt][3] * s1 + b1);
        }
    }
}

// ---------------------------------------------------------------------------
// scores + exp epilogue + partial row sums.
// grid (16 coltiles, 8 rowtiles, 64 heads), 256 threads.
// ---------------------------------------------------------------------------
__global__ void __launch_bounds__(256) k_scores(float* __restrict__ attn) {
    extern __shared__ float sm[];
    float* Qs = sm;                     // [128][68]
    float* Ks = sm + 128 * 68;          // [64][68]
    float* sPart = Ks + 64 * 68;        // [2][128]

    const int t = threadIdx.x;
    const int lane = t & 31, w = t >> 5;
    const int wm = w & 3, wn = w >> 2;
    const int g = lane >> 2, tg = lane & 3;
    const int z = blockIdx.z, b = z >> 3, h = z & 7;
    const int row0 = blockIdx.y * 128;
    const int col0 = blockIdx.x * 64;

    const float* Qg = g_Q + (size_t)b * L_ * D_ + h * DK_;
    const float* Kg = g_K + (size_t)b * L_ * D_ + h * DK_;
    float* attn_b = attn + (size_t)z * L_ * L_;

    #pragma unroll
    for (int i = 0; i < 8; i++) {
        int idx = t + i * 256, r = idx >> 4, c4 = (idx & 15) << 2;
        cp16(Qs + r * 68 + c4, Qg + (size_t)(row0 + r) * D_ + c4);
    }
    #pragma unroll
    for (int i = 0; i < 4; i++) {
        int idx = t + i * 256, r = idx >> 4, c4 = (idx & 15) << 2;
        cp16(Ks + r * 68 + c4, Kg + (size_t)(col0 + r) * D_ + c4);
    }
    CP_COMMIT();
    CP_WAIT0();
    __syncthreads();

    float acc[2][4][4] = {};
    #pragma unroll
    for (int ks = 0; ks < DK_; ks += 8) {
        float a[2][4], bf[4][2];
        #pragma unroll
        for (int mt = 0; mt < 2; mt++) {
            int r = wm * 32 + mt * 16 + g;
            a[mt][0] = tf32r(Qs[r * 68 + ks + tg]);
            a[mt][1] = tf32r(Qs[(r + 8) * 68 + ks + tg]);
            a[mt][2] = tf32r(Qs[r * 68 + ks + tg + 4]);
            a[mt][3] = tf32r(Qs[(r + 8) * 68 + ks + tg + 4]);
        }
        #pragma unroll
        for (int nt = 0; nt < 4; nt++) {
            int n = wn * 32 + nt * 8 + g;
            bf[nt][0] = tf32r(Ks[n * 68 + ks + tg]);
            bf[nt][1] = tf32r(Ks[n * 68 + ks + tg + 4]);
        }
        #pragma unroll
        for (int mt = 0; mt < 2; mt++)
            #pragma unroll
            for (int nt = 0; nt < 4; nt++)
                mma_tf32(acc[mt][nt], a[mt], bf[nt]);
    }

    // epilogue: E = exp(S/8), write E, accumulate row partials
    float rs[2][2] = {};
    #pragma unroll
    for (int mt = 0; mt < 2; mt++) {
        #pragma unroll
        for (int nt = 0; nt < 4; nt++) {
            int rl = wm * 32 + mt * 16 + g;
            int r = row0 + rl;
            int c = col0 + wn * 32 + nt * 8 + tg * 2;
            float e0 = __expf(acc[mt][nt][0] * 0.125f);
            float e1 = __expf(acc[mt][nt][1] * 0.125f);
            float e2 = __expf(acc[mt][nt][2] * 0.125f);
            float e3 = __expf(acc[mt][nt][3] * 0.125f);
            *(float2*)(attn_b + (size_t)r * L_ + c) = make_float2(e0, e1);
            *(float2*)(attn_b + (size_t)(r + 8) * L_ + c) = make_float2(e2, e3);
            rs[mt][0] += e0 + e1;
            rs[mt][1] += e2 + e3;
        }
    }
    #pragma unroll
    for (int mt = 0; mt < 2; mt++) {
        #pragma unroll
        for (int j = 0; j < 2; j++) {
            rs[mt][j] += __shfl_xor_sync(~0u, rs[mt][j], 1);
            rs[mt][j] += __shfl_xor_sync(~0u, rs[mt][j], 2);
        }
        if (tg == 0) {
            int rl = wm * 32 + mt * 16 + g;
            sPart[wn * 128 + rl] = rs[mt][0];
            sPart[wn * 128 + rl + 8] = rs[mt][1];
        }
    }
    __syncthreads();
    if (t < 128)
        g_psum[((size_t)z * 16 + blockIdx.x) * L_ + row0 + t] =
            sPart[t] + sPart[128 + t];
}

// rinv = 1 / sum of 16 partials. grid 256 x 256 threads.
__global__ void k_rowsum() {
    int rid = blockIdx.x * 256 + threadIdx.x;   // z*1024 + row
    int z = rid >> 10, r = rid & 1023;
    float s = 0.f;
    #pragma unroll
    for (int ct = 0; ct < 16; ct++)
        s += g_psum[((size_t)z * 16 + ct) * L_ + r];
    g_rinv[rid] = 1.0f / s;
}

// ---------------------------------------------------------------------------
// GEMM wrapper kernels
// ---------------------------------------------------------------------------
__global__ void __launch_bounds__(NTHR) k_proj_q(const float* __restrict__ A,
        const float* __restrict__ W, const float* __restrict__ bias) {
    gemm_pipe<false>(A, W, bias, g_Q, D_, D_, D_, D_, nullptr, nullptr);
}
__global__ void __launch_bounds__(NTHR) k_proj_k(const float* __restrict__ A,
        const float* __restrict__ W, const float* __restrict__ bias) {
    gemm_pipe<false>(A, W, bias, g_K, D_, D_, D_, D_, nullptr, nullptr);
}
__global__ void __launch_bounds__(NTHR) k_proj_v(const float* __restrict__ A,
        const float* __restrict__ W, const float* __restrict__ bias) {
    gemm_pipe<false>(A, W, bias, g_V, D_, D_, D_, D_, nullptr, nullptr);
}

// O = (E @ V) * rinv; also writes normalized attn. grid (1, 8, 64)
__global__ void __launch_bounds__(NTHR) k_attnv(float* __restrict__ attn) {
    int z = blockIdx.z, b = z >> 3, h = z & 7;
    float* Ab = attn + (size_t)z * L_ * L_;
    const float* Bb = g_V + (size_t)b * L_ * D_ + h * DK_;
    float* Cb = g_O + (size_t)b * L_ * D_ + h * DK_;
    gemm_pipe<true>(Ab, Bb, nullptr, Cb, L_, L_, D_, D_,
                    g_rinv + (size_t)z * L_, Ab);
}

__global__ void __launch_bounds__(NTHR) k_fc(const float* __restrict__ W,
        const float* __restrict__ bias) {
    gemm_pipe<false>(g_O, W, bias, g_O2, D_, D_, D_, D_, nullptr, nullptr);
}
__global__ void __launch_bounds__(NTHR) k_s2(const float* __restrict__ W,
        const float* __restrict__ bias) {
    gemm_pipe<false>(g_X, W, bias, g_O, D_, D_, D_, D_, nullptr, nullptr);
}

// ---------------------------------------------------------------------------
// lat = silu(latent) @ Ws1 + bs1 -> g_lat [B, 2D]. grid (8,8), 128 thr
// ---------------------------------------------------------------------------
__global__ void k_lat(const float* __restrict__ latent, const float* __restrict__ Ws1,
                      const float* __restrict__ bs1) {
    int b = blockIdx.x;
    __shared__ float sl[D_];
    for (int i = threadIdx.x; i < D_; i += 128) {
        float x = latent[b * D_ + i];
        sl[i] = x / (1.0f + __expf(-x));
    }
    __syncthreads();
    int j = blockIdx.y * 128 + threadIdx.x;
    float acc = bs1[j];
    for (int k = 0; k < D_; k++) acc += sl[k] * Ws1[(size_t)k * (2 * D_) + j];
    g_lat[b * (2 * D_) + j] = acc;
}

// film: X = silu( LN(o2; en) * (1+scale) + shift ). one block (128 thr) per row
__global__ void k_film(const float* __restrict__ en_g, const float* __restrict__ en_b) {
    int row = blockIdx.x;
    int b = row >> 10;
    int t = threadIdx.x;
    float4 v = ((const float4*)(g_O2 + (size_t)row * D_))[t];
    __shared__ float red[128];

    red[t] = v.x + v.y + v.z + v.w;
    __syncthreads();
    for (int s = 64; s > 0; s >>= 1) {
        if (t < s) red[t] += red[t + s];
        __syncthreads();
    }
    float mean = red[0] * (1.0f / D_);
    __syncthreads();

    float dx = v.x - mean, dy = v.y - mean, dz = v.z - mean, dw = v.w - mean;
    red[t] = dx * dx + dy * dy + dz * dz + dw * dw;
    __syncthreads();
    for (int s = 64; s > 0; s >>= 1) {
        if (t < s) red[t] += red[t + s];
        __syncthreads();
    }
    float rstd = rsqrtf(red[0] * (1.0f / D_) + 1e-5f);

    int j = t * 4;
    float4 g4 = ((const float4*)en_g)[t];
    float4 b4 = ((const float4*)en_b)[t];
    float4 sc = *(const float4*)(g_lat + b * (2 * D_) + j);
    float4 sh = *(const float4*)(g_lat + b * (2 * D_) + D_ + j);

    float4 o;
    {
        float h;
        h = (dx * rstd * g4.x + b4.x) * (1.0f + sc.x) + sh.x; o.x = h / (1.0f + __expf(-h));
        h = (dy * rstd * g4.y + b4.y) * (1.0f + sc.y) + sh.y; o.y = h / (1.0f + __expf(-h));
        h = (dz * rstd * g4.z + b4.z) * (1.0f + sc.z) + sh.z; o.z = h / (1.0f + __expf(-h));
        h = (dw * rstd * g4.w + b4.w) * (1.0f + sc.w) + sh.w; o.w = h / (1.0f + __expf(-h));
    }
    ((float4*)(g_X + (size_t)row * D_))[t] = o;
}

// out = LN(h2 + residual; ln, eps=1e-6). one block (128 thr) per row
__global__ void k_final(const float* __restrict__ resid, const float* __restrict__ ln_g,
                        const float* __restrict__ ln_b, float* __restrict__ out) {
    int row = blockIdx.x;
    int t = threadIdx.x;
    float4 v = ((const float4*)(g_O + (size_t)row * D_))[t];
    float4 r = ((const float4*)(resid + (size_t)row * D_))[t];
    v.x += r.x; v.y += r.y; v.z += r.z; v.w += r.w;
    __shared__ float red[128];

    red[t] = v.x + v.y + v.z + v.w;
    __syncthreads();
    for (int s = 64; s > 0; s >>= 1) {
        if (t < s) red[t] += red[t + s];
        __syncthreads();
    }
    float mean = red[0] * (1.0f / D_);
    __syncthreads();

    float dx = v.x - mean, dy = v.y - mean, dz = v.z - mean, dw = v.w - mean;
    red[t] = dx * dx + dy * dy + dz * dz + dw * dw;
    __syncthreads();
    for (int s = 64; s > 0; s >>= 1) {
        if (t < s) red[t] += red[t + s];
        __syncthreads();
    }
    float rstd = rsqrtf(red[0] * (1.0f / D_) + 1e-6f);

    float4 g4 = ((const float4*)ln_g)[t];
    float4 b4 = ((const float4*)ln_b)[t];
    float4 o;
    o.x = dx * rstd * g4.x + b4.x;
    o.y = dy * rstd * g4.y + b4.y;
    o.z = dz * rstd * g4.z + b4.z;
    o.w = dw * rstd * g4.w + b4.w;
    ((float4*)(out + (size_t)row * D_))[t] = o;
}

// ---------------------------------------------------------------------------
extern "C" void kernel_launch(void* const* d_in, const int* in_sizes, int n_in,
                              void* d_out, int out_size) {
    const float* q      = (const float*)d_in[0];
    const float* k      = (const float*)d_in[1];
    const float* v      = (const float*)d_in[2];
    const float* latent = (const float*)d_in[3];
    const float* Wq  = (const float*)d_in[4];
    const float* bq  = (const float*)d_in[5];
    const float* Wk  = (const float*)d_in[6];
    const float* bk  = (const float*)d_in[7];
    const float* Wv  = (const float*)d_in[8];
    const float* bv  = (const float*)d_in[9];
    const float* Wfc = (const float*)d_in[10];
    const float* bfc = (const float*)d_in[11];
    const float* Ws1 = (const float*)d_in[12];
    const float* bs1 = (const float*)d_in[13];
    const float* Ws2 = (const float*)d_in[14];
    const float* bs2 = (const float*)d_in[15];
    const float* en_g = (const float*)d_in[16];
    const float* en_b = (const float*)d_in[17];
    const float* ln_g = (const float*)d_in[18];
    const float* ln_b = (const float*)d_in[19];

    float* out  = (float*)d_out;
    float* attn = out + ATT_OFF;

    static bool attr_done = false;
    cudaFuncSetAttribute(k_proj_q, cudaFuncAttributeMaxDynamicSharedMemorySize, SMEM_GEMM);
    cudaFuncSetAttribute(k_proj_k, cudaFuncAttributeMaxDynamicSharedMemorySize, SMEM_GEMM);
    cudaFuncSetAttribute(k_proj_v, cudaFuncAttributeMaxDynamicSharedMemorySize, SMEM_GEMM);
    cudaFuncSetAttribute(k_attnv,  cudaFuncAttributeMaxDynamicSharedMemorySize, SMEM_GEMM);
    cudaFuncSetAttribute(k_fc,     cudaFuncAttributeMaxDynamicSharedMemorySize, SMEM_GEMM);
    cudaFuncSetAttribute(k_s2,     cudaFuncAttributeMaxDynamicSharedMemorySize, SMEM_GEMM);
    cudaFuncSetAttribute(k_scores, cudaFuncAttributeMaxDynamicSharedMemorySize, SMEM_SC);
    (void)attr_done;

    dim3 t256(NTHR);
    dim3 gProj(D_ / BN, BL_ / BM);          // (8, 64)

    k_proj_q<<<gProj, t256, SMEM_GEMM>>>(q, Wq, bq);
    k_proj_k<<<gProj, t256, SMEM_GEMM>>>(k, Wk, bk);
    k_proj_v<<<gProj, t256, SMEM_GEMM>>>(v, Wv, bv);

    k_scores<<<dim3(L_ / 64, L_ / 128, B_ * H_), t256, SMEM_SC>>>(attn);
    k_rowsum<<<(B_ * H_ * L_) / 256, 256>>>();
    k_attnv<<<dim3(1, L_ / BM, B_ * H_), t256, SMEM_GEMM>>>(attn);

    k_fc<<<gProj, t256, SMEM_GEMM>>>(Wfc, bfc);
    k_lat<<<dim3(B_, 8), 128>>>(latent, Ws1, bs1);
    k_film<<<BL_, 128>>>(en_g, en_b);
    k_s2<<<gProj, t256, SMEM_GEMM>>>(Ws2, bs2);
    k_final<<<BL_, 128>>>(q, ln_g, ln_b, out);
}